// round 2
// baseline (speedup 1.0000x reference)
#include <cuda_runtime.h>

#define MAXB      524288
#define P1_ROWS   8
#define P1_TPB    256
#define P1_MAXBLK 512
#define P2_ROWS   4
#define P2_TPB    256

// Scratch (no allocations allowed -> __device__ globals)
__device__ float gMp[136 * 12];          // packed symmetric quadratic-form coeffs
__device__ float gQ[MAXB * 12];          // per-row q features (25 MB)
__device__ float gPartial[P1_MAXBLK * 90];
__device__ float gW2[128 * 12];          // folded BN weights
__device__ float gB2[128];               // folded BN bias

// ---------------------------------------------------------------------------
// Setup: simulate the 3 circuits (16 basis columns each) in shared memory,
// then build Mp[pair][12].
// ---------------------------------------------------------------------------
__global__ void setup_kernel(const float* __restrict__ p1,
                             const float* __restrict__ p2,
                             const float* __restrict__ p3)
{
    __shared__ float sUr[3][16][16];   // [circuit][k][column]
    __shared__ float sUi[3][16][16];
    __shared__ unsigned char pa[136], pb[136];
    int tid = threadIdx.x;

    if (tid < 48) {
        int ci = tid >> 4;
        int c  = tid & 15;
        const float* P = (ci == 0) ? p1 : (ci == 1) ? p2 : p3;
        float* R = &sUr[ci][0][c];     // element k at R[k*16]
        float* I = &sUi[ci][0][c];
        for (int k = 0; k < 16; k++) { R[k * 16] = (k == c) ? 1.f : 0.f; I[k * 16] = 0.f; }

        // generic 1-qubit complex gate; bit = 8 >> qubit (wire 0 = MSB)
        auto ap1 = [&](int bit, float g00r, float g00i, float g01r, float g01i,
                                float g10r, float g10i, float g11r, float g11i) {
            for (int k = 0; k < 16; k++) {
                if (k & bit) continue;
                int k1 = k + bit;
                float a0r = R[k * 16],  a0i = I[k * 16];
                float a1r = R[k1 * 16], a1i = I[k1 * 16];
                R[k * 16]  = g00r * a0r - g00i * a0i + g01r * a1r - g01i * a1i;
                I[k * 16]  = g00r * a0i + g00i * a0r + g01r * a1i + g01i * a1r;
                R[k1 * 16] = g10r * a0r - g10i * a0i + g11r * a1r - g11i * a1i;
                I[k1 * 16] = g10r * a0i + g10i * a0r + g11r * a1i + g11i * a1r;
            }
        };
        auto cnot = [&](int cb, int tb) {
            for (int k = 0; k < 16; k++) {
                if ((k & cb) && !(k & tb)) {
                    int k1 = k + tb;
                    float tr = R[k * 16]; R[k * 16] = R[k1 * 16]; R[k1 * 16] = tr;
                    float ti = I[k * 16]; I[k * 16] = I[k1 * 16]; I[k1 * 16] = ti;
                }
            }
        };
        auto cz = [&](int cb, int tb) {
            for (int k = 0; k < 16; k++)
                if ((k & cb) && (k & tb)) { R[k * 16] = -R[k * 16]; I[k * 16] = -I[k * 16]; }
        };

        const float hs = 0.7071067811865476f;
        for (int l = 0; l < 2; l++) {
            for (int q = 0; q < 4; q++) ap1(8 >> q, hs, 0, hs, 0, hs, 0, -hs, 0);
            for (int q = 0; q < 4; q++) {
                float ty = P[l * 12 + q], tz = P[l * 12 + q + 4], tx = P[l * 12 + q + 8];
                float cy = cosf(0.5f * ty), sy = sinf(0.5f * ty);
                ap1(8 >> q, cy, 0, -sy, 0, sy, 0, cy, 0);                 // RY
                float cc = cosf(0.5f * tz), sc = sinf(0.5f * tz);
                ap1(8 >> q, cc, -sc, 0, 0, 0, 0, cc, sc);                 // RZ
                float cx = cosf(0.5f * tx), sx = sinf(0.5f * tx);
                ap1(8 >> q, cx, 0, 0, -sx, 0, -sx, cx, 0);                // RX
            }
            for (int q = 0; q < 4; q++) ap1(8 >> q, 1, 0, 0, 0, 0, 0, 0, 1);   // S
            for (int i = 0; i < 3; i++) { cnot(8 >> i, 8 >> (i + 1)); cz(8 >> i, 8 >> (i + 1)); }
            cnot(1, 8); cz(1, 8);  // control qubit 3 (bit0), target qubit 0 (bit3)
        }
    }
    if (tid == 0) {
        int p = 0;
        for (int a = 0; a < 16; a++)
            for (int b = a; b < 16; b++) { pa[p] = (unsigned char)a; pb[p] = (unsigned char)b; p++; }
    }
    __syncthreads();

    // M_j[a][b] = sum_k sign(k) * (Ur[k][a]Ur[k][b] + Ui[k][a]Ui[k][b]); pack a<=b, 2x off-diag
    for (int idx = tid; idx < 136 * 12; idx += blockDim.x) {
        int p = idx / 12, j = idx - p * 12;
        int ci = j >> 2, qb = j & 3;
        int a = pa[p], b = pb[p];
        int bit = 8 >> qb;
        float s = 0.f;
        for (int k = 0; k < 16; k++) {
            float v = sUr[ci][k][a] * sUr[ci][k][b] + sUi[ci][k][a] * sUi[ci][k][b];
            s += (k & bit) ? -v : v;
        }
        if (a != b) s *= 2.f;
        gMp[idx] = s;
    }
}

// ---------------------------------------------------------------------------
// Pass 1: q[b][12] = x^T M_j x / (x.x); accumulate 90 moments per block.
// ---------------------------------------------------------------------------
__global__ void __launch_bounds__(P1_TPB) pass1_kernel(const float* __restrict__ x, int B)
{
    __shared__ float sM[136 * 12];
    __shared__ float sred[8 * 90];
    for (int i = threadIdx.x; i < 136 * 12; i += P1_TPB) sM[i] = gMp[i];
    __syncthreads();

    float mom[90];
#pragma unroll
    for (int v = 0; v < 90; v++) mom[v] = 0.f;

    int base = blockIdx.x * (P1_TPB * P1_ROWS) + threadIdx.x;
    for (int t = 0; t < P1_ROWS; t++) {
        int row = base + t * P1_TPB;
        if (row < B) {
            const float4* xp = (const float4*)(x + (size_t)row * 16);
            float4 x0 = xp[0], x1 = xp[1], x2 = xp[2], x3 = xp[3];
            float xx[16] = {x0.x, x0.y, x0.z, x0.w, x1.x, x1.y, x1.z, x1.w,
                            x2.x, x2.y, x2.z, x2.w, x3.x, x3.y, x3.z, x3.w};
            float dot = 0.f;
#pragma unroll
            for (int i = 0; i < 16; i++) dot += xx[i] * xx[i];
            float inv = 1.0f / dot;

            float q[12];
#pragma unroll
            for (int j = 0; j < 12; j++) q[j] = 0.f;

            int p = 0;
#pragma unroll
            for (int i = 0; i < 16; i++) {
#pragma unroll
                for (int k = i; k < 16; k++) {
                    float pv = xx[i] * xx[k];
                    const float4* mp = (const float4*)(sM + p * 12);
                    float4 m0 = mp[0], m1 = mp[1], m2 = mp[2];
                    q[0] += m0.x * pv; q[1] += m0.y * pv; q[2]  += m0.z * pv; q[3]  += m0.w * pv;
                    q[4] += m1.x * pv; q[5] += m1.y * pv; q[6]  += m1.z * pv; q[7]  += m1.w * pv;
                    q[8] += m2.x * pv; q[9] += m2.y * pv; q[10] += m2.z * pv; q[11] += m2.w * pv;
                    p++;
                }
            }
#pragma unroll
            for (int j = 0; j < 12; j++) q[j] *= inv;

            float4* qo = (float4*)(gQ + (size_t)row * 12);
            qo[0] = make_float4(q[0], q[1], q[2],  q[3]);
            qo[1] = make_float4(q[4], q[5], q[6],  q[7]);
            qo[2] = make_float4(q[8], q[9], q[10], q[11]);

#pragma unroll
            for (int j = 0; j < 12; j++) mom[j] += q[j];
            int m = 12;
#pragma unroll
            for (int j = 0; j < 12; j++)
#pragma unroll
                for (int k = j; k < 12; k++) { mom[m] += q[j] * q[k]; m++; }
        }
    }

    int lane = threadIdx.x & 31, warp = threadIdx.x >> 5;
#pragma unroll
    for (int v = 0; v < 90; v++) {
        float s = mom[v];
        s += __shfl_down_sync(0xffffffffu, s, 16);
        s += __shfl_down_sync(0xffffffffu, s, 8);
        s += __shfl_down_sync(0xffffffffu, s, 4);
        s += __shfl_down_sync(0xffffffffu, s, 2);
        s += __shfl_down_sync(0xffffffffu, s, 1);
        if (lane == 0) sred[warp * 90 + v] = s;
    }
    __syncthreads();
    if (threadIdx.x < 90) {
        float s = 0.f;
#pragma unroll
        for (int w = 0; w < 8; w++) s += sred[w * 90 + threadIdx.x];
        gPartial[blockIdx.x * 90 + threadIdx.x] = s;
    }
}

// ---------------------------------------------------------------------------
// Finalize: fold BatchNorm into W2/B2 using q moments (double precision).
// ---------------------------------------------------------------------------
__global__ void finalize_kernel(const float* __restrict__ fc_w, const float* __restrict__ fc_b,
                                const float* __restrict__ gamma, const float* __restrict__ beta,
                                int B, int nblocks)
{
    __shared__ double mom[90];
    int tid = threadIdx.x;
    if (tid < 90) {
        double s = 0.0;
        for (int b = 0; b < nblocks; b++) s += (double)gPartial[b * 90 + tid];
        mom[tid] = s;
    }
    __syncthreads();
    if (tid < 128) {
        double invB = 1.0 / (double)B;
        double m[12], wv[12];
        for (int j = 0; j < 12; j++) { m[j] = mom[j] * invB; wv[j] = (double)fc_w[tid * 12 + j]; }
        double mu = (double)fc_b[tid];
        for (int j = 0; j < 12; j++) mu += wv[j] * m[j];
        double var = 0.0;
        int idx = 12;
        for (int j = 0; j < 12; j++)
            for (int k = j; k < 12; k++) {
                double cjk = mom[idx] * invB - m[j] * m[k];
                double t = wv[j] * wv[k] * cjk;
                var += (j == k) ? t : 2.0 * t;
                idx++;
            }
        double s = (double)gamma[tid] / sqrt(var + 1e-5);
        for (int j = 0; j < 12; j++) gW2[tid * 12 + j] = (float)(wv[j] * s);
        gB2[tid] = (float)((double)beta[tid] + s * ((double)fc_b[tid] - mu));
    }
}

// ---------------------------------------------------------------------------
// Pass 2: out[b][128] = relu(q[b] . W2[c] + B2[c])
// ---------------------------------------------------------------------------
__global__ void __launch_bounds__(P2_TPB) pass2_kernel(float* __restrict__ out, int B)
{
    __shared__ float sW[128 * 12];
    __shared__ float sB[128];
    for (int i = threadIdx.x; i < 128 * 12; i += P2_TPB) sW[i] = gW2[i];
    if (threadIdx.x < 128) sB[threadIdx.x] = gB2[threadIdx.x];
    __syncthreads();

    int base = blockIdx.x * (P2_TPB * P2_ROWS) + threadIdx.x;
    float qa[P2_ROWS][12];
    int rows[P2_ROWS];
#pragma unroll
    for (int r = 0; r < P2_ROWS; r++) {
        rows[r] = base + r * P2_TPB;
        if (rows[r] < B) {
            const float4* qp = (const float4*)(gQ + (size_t)rows[r] * 12);
            float4 q0 = qp[0], q1 = qp[1], q2 = qp[2];
            qa[r][0] = q0.x; qa[r][1] = q0.y; qa[r][2]  = q0.z; qa[r][3]  = q0.w;
            qa[r][4] = q1.x; qa[r][5] = q1.y; qa[r][6]  = q1.z; qa[r][7]  = q1.w;
            qa[r][8] = q2.x; qa[r][9] = q2.y; qa[r][10] = q2.z; qa[r][11] = q2.w;
        }
    }

    for (int quad = 0; quad < 32; quad++) {
        float w[48];
        const float4* wp = (const float4*)(sW + quad * 48);
#pragma unroll
        for (int u = 0; u < 12; u++) {
            float4 t4 = wp[u];
            w[u * 4] = t4.x; w[u * 4 + 1] = t4.y; w[u * 4 + 2] = t4.z; w[u * 4 + 3] = t4.w;
        }
        float4 bias = ((const float4*)sB)[quad];
#pragma unroll
        for (int r = 0; r < P2_ROWS; r++) {
            if (rows[r] >= B) continue;
            float a0 = bias.x, a1 = bias.y, a2 = bias.z, a3 = bias.w;
#pragma unroll
            for (int j = 0; j < 12; j++) {
                float qv = qa[r][j];
                a0 += qv * w[j]; a1 += qv * w[12 + j]; a2 += qv * w[24 + j]; a3 += qv * w[36 + j];
            }
            float4 o = make_float4(fmaxf(a0, 0.f), fmaxf(a1, 0.f), fmaxf(a2, 0.f), fmaxf(a3, 0.f));
            *((float4*)(out + (size_t)rows[r] * 128 + quad * 4)) = o;
        }
    }
}

// ---------------------------------------------------------------------------
extern "C" void kernel_launch(void* const* d_in, const int* in_sizes, int n_in,
                              void* d_out, int out_size)
{
    const float* x  = (const float*)d_in[0];
    const float* p1 = (const float*)d_in[1];
    const float* p2 = (const float*)d_in[2];
    const float* p3 = (const float*)d_in[3];
    const float* fw = (const float*)d_in[4];
    const float* fb = (const float*)d_in[5];
    const float* gm = (const float*)d_in[6];
    const float* bt = (const float*)d_in[7];
    float* out = (float*)d_out;

    int B  = in_sizes[0] / 16;
    if (B > MAXB) B = MAXB;   // scratch bound safety (B is 524288 in this dataset)
    int g1 = (B + P1_TPB * P1_ROWS - 1) / (P1_TPB * P1_ROWS);
    if (g1 > P1_MAXBLK) g1 = P1_MAXBLK;
    int g2 = (B + P2_TPB * P2_ROWS - 1) / (P2_TPB * P2_ROWS);

    setup_kernel<<<1, 128>>>(p1, p2, p3);
    pass1_kernel<<<g1, P1_TPB>>>(x, B);
    finalize_kernel<<<1, 128>>>(fw, fb, gm, bt, B, g1);
    pass2_kernel<<<g2, P2_TPB>>>(out, B);
}

// round 3
// speedup vs baseline: 1.3533x; 1.3533x over previous
#include <cuda_runtime.h>

#define MAXB      524288
#define P1_ROWS   4
#define P1_TPB    256
#define ST_ROWS   8
#define ST_TPB    256
#define ST_MAXBLK 512
#define P2_TPB    256
#define P2_BLKS   512

// Scratch (no allocations allowed -> __device__ globals)
__device__ float gMp[136 * 12];          // packed symmetric quadratic-form coeffs
__device__ float gQ[MAXB * 12];          // per-row q features (25 MB)
__device__ float gPartial[ST_MAXBLK * 90];
__device__ float gW2[128 * 12];          // folded BN weights
__device__ float gB2[128];               // folded BN bias

// ---------------------------------------------------------------------------
// Setup: simulate the 3 circuits (16 basis columns each) in shared memory,
// then build Mp[pair][12].
// ---------------------------------------------------------------------------
__global__ void setup_kernel(const float* __restrict__ p1,
                             const float* __restrict__ p2,
                             const float* __restrict__ p3)
{
    __shared__ float sUr[3][16][16];   // [circuit][k][column]
    __shared__ float sUi[3][16][16];
    __shared__ unsigned char pa[136], pb[136];
    int tid = threadIdx.x;

    if (tid < 48) {
        int ci = tid >> 4;
        int c  = tid & 15;
        const float* P = (ci == 0) ? p1 : (ci == 1) ? p2 : p3;
        float* R = &sUr[ci][0][c];     // element k at R[k*16]
        float* I = &sUi[ci][0][c];
        for (int k = 0; k < 16; k++) { R[k * 16] = (k == c) ? 1.f : 0.f; I[k * 16] = 0.f; }

        auto ap1 = [&](int bit, float g00r, float g00i, float g01r, float g01i,
                                float g10r, float g10i, float g11r, float g11i) {
            for (int k = 0; k < 16; k++) {
                if (k & bit) continue;
                int k1 = k + bit;
                float a0r = R[k * 16],  a0i = I[k * 16];
                float a1r = R[k1 * 16], a1i = I[k1 * 16];
                R[k * 16]  = g00r * a0r - g00i * a0i + g01r * a1r - g01i * a1i;
                I[k * 16]  = g00r * a0i + g00i * a0r + g01r * a1i + g01i * a1r;
                R[k1 * 16] = g10r * a0r - g10i * a0i + g11r * a1r - g11i * a1i;
                I[k1 * 16] = g10r * a0i + g10i * a0r + g11r * a1i + g11i * a1r;
            }
        };
        auto cnot = [&](int cb, int tb) {
            for (int k = 0; k < 16; k++) {
                if ((k & cb) && !(k & tb)) {
                    int k1 = k + tb;
                    float tr = R[k * 16]; R[k * 16] = R[k1 * 16]; R[k1 * 16] = tr;
                    float ti = I[k * 16]; I[k * 16] = I[k1 * 16]; I[k1 * 16] = ti;
                }
            }
        };
        auto cz = [&](int cb, int tb) {
            for (int k = 0; k < 16; k++)
                if ((k & cb) && (k & tb)) { R[k * 16] = -R[k * 16]; I[k * 16] = -I[k * 16]; }
        };

        const float hs = 0.7071067811865476f;
        for (int l = 0; l < 2; l++) {
            for (int q = 0; q < 4; q++) ap1(8 >> q, hs, 0, hs, 0, hs, 0, -hs, 0);
            for (int q = 0; q < 4; q++) {
                float ty = P[l * 12 + q], tz = P[l * 12 + q + 4], tx = P[l * 12 + q + 8];
                float cy = cosf(0.5f * ty), sy = sinf(0.5f * ty);
                ap1(8 >> q, cy, 0, -sy, 0, sy, 0, cy, 0);                 // RY
                float cc = cosf(0.5f * tz), sc = sinf(0.5f * tz);
                ap1(8 >> q, cc, -sc, 0, 0, 0, 0, cc, sc);                 // RZ
                float cx = cosf(0.5f * tx), sx = sinf(0.5f * tx);
                ap1(8 >> q, cx, 0, 0, -sx, 0, -sx, cx, 0);                // RX
            }
            for (int q = 0; q < 4; q++) ap1(8 >> q, 1, 0, 0, 0, 0, 0, 0, 1);   // S
            for (int i = 0; i < 3; i++) { cnot(8 >> i, 8 >> (i + 1)); cz(8 >> i, 8 >> (i + 1)); }
            cnot(1, 8); cz(1, 8);
        }
    }
    if (tid == 0) {
        int p = 0;
        for (int a = 0; a < 16; a++)
            for (int b = a; b < 16; b++) { pa[p] = (unsigned char)a; pb[p] = (unsigned char)b; p++; }
    }
    __syncthreads();

    for (int idx = tid; idx < 136 * 12; idx += blockDim.x) {
        int p = idx / 12, j = idx - p * 12;
        int ci = j >> 2, qb = j & 3;
        int a = pa[p], b = pb[p];
        int bit = 8 >> qb;
        float s = 0.f;
        for (int k = 0; k < 16; k++) {
            float v = sUr[ci][k][a] * sUr[ci][k][b] + sUi[ci][k][a] * sUi[ci][k][b];
            s += (k & bit) ? -v : v;
        }
        if (a != b) s *= 2.f;
        gMp[idx] = s;
    }
}

// ---------------------------------------------------------------------------
// Pass 1: q[b][12] = x^T M_j x / (x.x). No moment accumulation (low regs).
// ---------------------------------------------------------------------------
__global__ void __launch_bounds__(P1_TPB) pass1_kernel(const float* __restrict__ x, int B)
{
    __shared__ float sM[136 * 12];
    for (int i = threadIdx.x; i < 136 * 12; i += P1_TPB) sM[i] = gMp[i];
    __syncthreads();

    int base = blockIdx.x * (P1_TPB * P1_ROWS) + threadIdx.x;
#pragma unroll
    for (int t = 0; t < P1_ROWS; t++) {
        int row = base + t * P1_TPB;
        if (row >= B) continue;
        const float4* xp = (const float4*)(x + (size_t)row * 16);
        float4 x0 = xp[0], x1 = xp[1], x2 = xp[2], x3 = xp[3];
        float xx[16] = {x0.x, x0.y, x0.z, x0.w, x1.x, x1.y, x1.z, x1.w,
                        x2.x, x2.y, x2.z, x2.w, x3.x, x3.y, x3.z, x3.w};
        float dot = 0.f;
#pragma unroll
        for (int i = 0; i < 16; i++) dot += xx[i] * xx[i];
        float inv = 1.0f / dot;

        float q[12];
#pragma unroll
        for (int j = 0; j < 12; j++) q[j] = 0.f;

        int p = 0;
#pragma unroll
        for (int i = 0; i < 16; i++) {
#pragma unroll
            for (int k = i; k < 16; k++) {
                float pv = xx[i] * xx[k];
                const float4* mp = (const float4*)(sM + p * 12);
                float4 m0 = mp[0], m1 = mp[1], m2 = mp[2];
                q[0] += m0.x * pv; q[1] += m0.y * pv; q[2]  += m0.z * pv; q[3]  += m0.w * pv;
                q[4] += m1.x * pv; q[5] += m1.y * pv; q[6]  += m1.z * pv; q[7]  += m1.w * pv;
                q[8] += m2.x * pv; q[9] += m2.y * pv; q[10] += m2.z * pv; q[11] += m2.w * pv;
                p++;
            }
        }
        float4* qo = (float4*)(gQ + (size_t)row * 12);
        qo[0] = make_float4(q[0] * inv, q[1] * inv, q[2]  * inv, q[3]  * inv);
        qo[1] = make_float4(q[4] * inv, q[5] * inv, q[6]  * inv, q[7]  * inv);
        qo[2] = make_float4(q[8] * inv, q[9] * inv, q[10] * inv, q[11] * inv);
    }
}

// ---------------------------------------------------------------------------
// Stats: read gQ, accumulate 90 moments (12 means + 78 second moments).
// ---------------------------------------------------------------------------
__global__ void __launch_bounds__(ST_TPB, 2) stats_kernel(int B)
{
    __shared__ float sred[8 * 90];
    float mom[90];
#pragma unroll
    for (int v = 0; v < 90; v++) mom[v] = 0.f;

    int base = blockIdx.x * (ST_TPB * ST_ROWS) + threadIdx.x;
#pragma unroll
    for (int t = 0; t < ST_ROWS; t++) {
        int row = base + t * ST_TPB;
        if (row >= B) continue;
        const float4* qp = (const float4*)(gQ + (size_t)row * 12);
        float4 q0 = qp[0], q1 = qp[1], q2 = qp[2];
        float q[12] = {q0.x, q0.y, q0.z, q0.w, q1.x, q1.y, q1.z, q1.w,
                       q2.x, q2.y, q2.z, q2.w};
#pragma unroll
        for (int j = 0; j < 12; j++) mom[j] += q[j];
        int m = 12;
#pragma unroll
        for (int j = 0; j < 12; j++)
#pragma unroll
            for (int k = j; k < 12; k++) { mom[m] += q[j] * q[k]; m++; }
    }

    int lane = threadIdx.x & 31, warp = threadIdx.x >> 5;
#pragma unroll
    for (int v = 0; v < 90; v++) {
        float s = mom[v];
        s += __shfl_down_sync(0xffffffffu, s, 16);
        s += __shfl_down_sync(0xffffffffu, s, 8);
        s += __shfl_down_sync(0xffffffffu, s, 4);
        s += __shfl_down_sync(0xffffffffu, s, 2);
        s += __shfl_down_sync(0xffffffffu, s, 1);
        if (lane == 0) sred[warp * 90 + v] = s;
    }
    __syncthreads();
    if (threadIdx.x < 90) {
        float s = 0.f;
#pragma unroll
        for (int w = 0; w < 8; w++) s += sred[w * 90 + threadIdx.x];
        gPartial[blockIdx.x * 90 + threadIdx.x] = s;
    }
}

// ---------------------------------------------------------------------------
// Finalize: fold BatchNorm into W2/B2 using q moments (double precision).
// ---------------------------------------------------------------------------
__global__ void finalize_kernel(const float* __restrict__ fc_w, const float* __restrict__ fc_b,
                                const float* __restrict__ gamma, const float* __restrict__ beta,
                                int B, int nblocks)
{
    __shared__ double mom[90];
    int tid = threadIdx.x;
    if (tid < 90) {
        double s = 0.0;
        for (int b = 0; b < nblocks; b++) s += (double)gPartial[b * 90 + tid];
        mom[tid] = s;
    }
    __syncthreads();
    if (tid < 128) {
        double invB = 1.0 / (double)B;
        double m[12], wv[12];
        for (int j = 0; j < 12; j++) { m[j] = mom[j] * invB; wv[j] = (double)fc_w[tid * 12 + j]; }
        double mu = (double)fc_b[tid];
        for (int j = 0; j < 12; j++) mu += wv[j] * m[j];
        double var = 0.0;
        int idx = 12;
        for (int j = 0; j < 12; j++)
            for (int k = j; k < 12; k++) {
                double cjk = mom[idx] * invB - m[j] * m[k];
                double t = wv[j] * wv[k] * cjk;
                var += (j == k) ? t : 2.0 * t;
                idx++;
            }
        double s = (double)gamma[tid] / sqrt(var + 1e-5);
        for (int j = 0; j < 12; j++) gW2[tid * 12 + j] = (float)(wv[j] * s);
        gB2[tid] = (float)((double)beta[tid] + s * ((double)fc_b[tid] - mu));
    }
}

// ---------------------------------------------------------------------------
// Pass 2: warp-per-row. Lane l owns output channels 4l..4l+3.
// One coalesced float4 store per lane = contiguous 512B per warp per row.
// ---------------------------------------------------------------------------
__global__ void __launch_bounds__(P2_TPB) pass2_kernel(float* __restrict__ out, int B)
{
    __shared__ float sW[128 * 12];
    for (int i = threadIdx.x; i < 128 * 12; i += P2_TPB) sW[i] = gW2[i];
    __syncthreads();

    int lane = threadIdx.x & 31;
    // per-lane weights: channels c0..c0+3, 12 each -> 48 regs
    int c0 = lane * 4;
    float w[48];
#pragma unroll
    for (int c = 0; c < 4; c++) {
        const float4* wp = (const float4*)(sW + (c0 + c) * 12);
        float4 a = wp[0], b4 = wp[1], d = wp[2];
        w[c * 12 + 0] = a.x;  w[c * 12 + 1] = a.y;  w[c * 12 + 2]  = a.z;  w[c * 12 + 3]  = a.w;
        w[c * 12 + 4] = b4.x; w[c * 12 + 5] = b4.y; w[c * 12 + 6]  = b4.z; w[c * 12 + 7]  = b4.w;
        w[c * 12 + 8] = d.x;  w[c * 12 + 9] = d.y;  w[c * 12 + 10] = d.z;  w[c * 12 + 11] = d.w;
    }
    float4 bias = ((const float4*)gB2)[lane];

    int warp_id = (blockIdx.x * (P2_TPB / 32)) + (threadIdx.x >> 5);
    int nwarps  = gridDim.x * (P2_TPB / 32);

    for (int row = warp_id; row < B; row += nwarps) {
        const float4* qp = (const float4*)(gQ + (size_t)row * 12);
        float4 q0 = qp[0], q1 = qp[1], q2 = qp[2];
        float q[12] = {q0.x, q0.y, q0.z, q0.w, q1.x, q1.y, q1.z, q1.w,
                       q2.x, q2.y, q2.z, q2.w};
        float a0 = bias.x, a1 = bias.y, a2 = bias.z, a3 = bias.w;
#pragma unroll
        for (int j = 0; j < 12; j++) {
            float qv = q[j];
            a0 += qv * w[j]; a1 += qv * w[12 + j]; a2 += qv * w[24 + j]; a3 += qv * w[36 + j];
        }
        float4 o = make_float4(fmaxf(a0, 0.f), fmaxf(a1, 0.f), fmaxf(a2, 0.f), fmaxf(a3, 0.f));
        *((float4*)(out + (size_t)row * 128 + c0)) = o;
    }
}

// ---------------------------------------------------------------------------
extern "C" void kernel_launch(void* const* d_in, const int* in_sizes, int n_in,
                              void* d_out, int out_size)
{
    const float* x  = (const float*)d_in[0];
    const float* p1 = (const float*)d_in[1];
    const float* p2 = (const float*)d_in[2];
    const float* p3 = (const float*)d_in[3];
    const float* fw = (const float*)d_in[4];
    const float* fb = (const float*)d_in[5];
    const float* gm = (const float*)d_in[6];
    const float* bt = (const float*)d_in[7];
    float* out = (float*)d_out;

    int B  = in_sizes[0] / 16;
    if (B > MAXB) B = MAXB;
    int g1 = (B + P1_TPB * P1_ROWS - 1) / (P1_TPB * P1_ROWS);
    int gs = (B + ST_TPB * ST_ROWS - 1) / (ST_TPB * ST_ROWS);
    if (gs > ST_MAXBLK) gs = ST_MAXBLK;

    setup_kernel<<<1, 128>>>(p1, p2, p3);
    pass1_kernel<<<g1, P1_TPB>>>(x, B);
    stats_kernel<<<gs, ST_TPB>>>(B);
    finalize_kernel<<<1, 128>>>(fw, fb, gm, bt, B, gs);
    pass2_kernel<<<P2_BLKS, P2_TPB>>>(out, B);
}

// round 4
// speedup vs baseline: 1.8103x; 1.3377x over previous
#include <cuda_runtime.h>

#define MAXB      524288
#define P1_ROWS   4
#define P1_TPB    256
#define ST_ROWS   8
#define ST_TPB    256
#define ST_MAXBLK 512
#define P2_TPB    256
#define P2_BLKS   1024

// Scratch (no allocations allowed -> __device__ globals)
__device__ float gMp[136 * 12];                 // packed symmetric quadratic-form coeffs
__device__ float gQ[MAXB * 12];                 // per-row q features (25 MB)
__device__ float gPartial[90 * ST_MAXBLK];      // [moment][block] (transposed!)
__device__ float gW2[128 * 12];                 // folded BN weights
__device__ float gB2[128];                      // folded BN bias

// ---------------------------------------------------------------------------
// Setup: register-resident simulation of the 3 circuits (one column per
// thread, 16 complex amplitudes in registers), then build Mp[pair][12].
// ---------------------------------------------------------------------------
__global__ void setup_kernel(const float* __restrict__ p1,
                             const float* __restrict__ p2,
                             const float* __restrict__ p3)
{
    __shared__ float sUr[3][16][16];   // [circuit][k][column]
    __shared__ float sUi[3][16][16];
    __shared__ unsigned char pa[136], pb[136];
    int tid = threadIdx.x;

    if (tid < 48) {
        int ci = tid >> 4;
        int c  = tid & 15;
        const float* P = (ci == 0) ? p1 : (ci == 1) ? p2 : p3;
        float R[16], I[16];
#pragma unroll
        for (int k = 0; k < 16; k++) { R[k] = (k == c) ? 1.f : 0.f; I[k] = 0.f; }

        // generic 1-qubit complex gate; bit must resolve to a constant
        auto ap1 = [&](int bit, float g00r, float g00i, float g01r, float g01i,
                                float g10r, float g10i, float g11r, float g11i) {
#pragma unroll
            for (int k = 0; k < 16; k++) {
                if (k & bit) continue;
                int k1 = k + bit;
                float a0r = R[k],  a0i = I[k];
                float a1r = R[k1], a1i = I[k1];
                R[k]  = g00r * a0r - g00i * a0i + g01r * a1r - g01i * a1i;
                I[k]  = g00r * a0i + g00i * a0r + g01r * a1i + g01i * a1r;
                R[k1] = g10r * a0r - g10i * a0i + g11r * a1r - g11i * a1i;
                I[k1] = g10r * a0i + g10i * a0r + g11r * a1i + g11i * a1r;
            }
        };
        auto cnot = [&](int cb, int tb) {
#pragma unroll
            for (int k = 0; k < 16; k++) {
                if ((k & cb) && !(k & tb)) {
                    int k1 = k + tb;
                    float tr = R[k]; R[k] = R[k1]; R[k1] = tr;
                    float ti = I[k]; I[k] = I[k1]; I[k1] = ti;
                }
            }
        };
        auto cz = [&](int cb, int tb) {
#pragma unroll
            for (int k = 0; k < 16; k++)
                if ((k & cb) && (k & tb)) { R[k] = -R[k]; I[k] = -I[k]; }
        };

        const float hs = 0.7071067811865476f;
#pragma unroll
        for (int l = 0; l < 2; l++) {
#pragma unroll
            for (int q = 0; q < 4; q++) ap1(8 >> q, hs, 0, hs, 0, hs, 0, -hs, 0);
#pragma unroll
            for (int q = 0; q < 4; q++) {
                float ty = P[l * 12 + q], tz = P[l * 12 + q + 4], tx = P[l * 12 + q + 8];
                float cy = cosf(0.5f * ty), sy = sinf(0.5f * ty);
                ap1(8 >> q, cy, 0, -sy, 0, sy, 0, cy, 0);                 // RY
                float cc = cosf(0.5f * tz), sc = sinf(0.5f * tz);
                ap1(8 >> q, cc, -sc, 0, 0, 0, 0, cc, sc);                 // RZ
                float cx = cosf(0.5f * tx), sx = sinf(0.5f * tx);
                ap1(8 >> q, cx, 0, 0, -sx, 0, -sx, cx, 0);                // RX
            }
#pragma unroll
            for (int q = 0; q < 4; q++) ap1(8 >> q, 1, 0, 0, 0, 0, 0, 0, 1);   // S
#pragma unroll
            for (int i = 0; i < 3; i++) { cnot(8 >> i, 8 >> (i + 1)); cz(8 >> i, 8 >> (i + 1)); }
            cnot(1, 8); cz(1, 8);   // control qubit 3 (bit0), target qubit 0 (bit3)
        }
#pragma unroll
        for (int k = 0; k < 16; k++) { sUr[ci][k][c] = R[k]; sUi[ci][k][c] = I[k]; }
    }
    if (tid == 0) {
        int p = 0;
        for (int a = 0; a < 16; a++)
            for (int b = a; b < 16; b++) { pa[p] = (unsigned char)a; pb[p] = (unsigned char)b; p++; }
    }
    __syncthreads();

    // M_j[a][b] = sum_k sign(k) * (Ur[k][a]Ur[k][b] + Ui[k][a]Ui[k][b]); pack a<=b, 2x off-diag
    for (int idx = tid; idx < 136 * 12; idx += blockDim.x) {
        int p = idx / 12, j = idx - p * 12;
        int ci = j >> 2, qb = j & 3;
        int a = pa[p], b = pb[p];
        int bit = 8 >> qb;
        float s = 0.f;
        for (int k = 0; k < 16; k++) {
            float v = sUr[ci][k][a] * sUr[ci][k][b] + sUi[ci][k][a] * sUi[ci][k][b];
            s += (k & bit) ? -v : v;
        }
        if (a != b) s *= 2.f;
        gMp[idx] = s;
    }
}

// ---------------------------------------------------------------------------
// Pass 1: q[b][12] = x^T M_j x / (x.x). No moment accumulation (low regs).
// ---------------------------------------------------------------------------
__global__ void __launch_bounds__(P1_TPB) pass1_kernel(const float* __restrict__ x, int B)
{
    __shared__ float sM[136 * 12];
    for (int i = threadIdx.x; i < 136 * 12; i += P1_TPB) sM[i] = gMp[i];
    __syncthreads();

    int base = blockIdx.x * (P1_TPB * P1_ROWS) + threadIdx.x;
#pragma unroll
    for (int t = 0; t < P1_ROWS; t++) {
        int row = base + t * P1_TPB;
        if (row >= B) continue;
        const float4* xp = (const float4*)(x + (size_t)row * 16);
        float4 x0 = xp[0], x1 = xp[1], x2 = xp[2], x3 = xp[3];
        float xx[16] = {x0.x, x0.y, x0.z, x0.w, x1.x, x1.y, x1.z, x1.w,
                        x2.x, x2.y, x2.z, x2.w, x3.x, x3.y, x3.z, x3.w};
        float dot = 0.f;
#pragma unroll
        for (int i = 0; i < 16; i++) dot += xx[i] * xx[i];
        float inv = 1.0f / dot;

        float q[12];
#pragma unroll
        for (int j = 0; j < 12; j++) q[j] = 0.f;

        int p = 0;
#pragma unroll
        for (int i = 0; i < 16; i++) {
#pragma unroll
            for (int k = i; k < 16; k++) {
                float pv = xx[i] * xx[k];
                const float4* mp = (const float4*)(sM + p * 12);
                float4 m0 = mp[0], m1 = mp[1], m2 = mp[2];
                q[0] += m0.x * pv; q[1] += m0.y * pv; q[2]  += m0.z * pv; q[3]  += m0.w * pv;
                q[4] += m1.x * pv; q[5] += m1.y * pv; q[6]  += m1.z * pv; q[7]  += m1.w * pv;
                q[8] += m2.x * pv; q[9] += m2.y * pv; q[10] += m2.z * pv; q[11] += m2.w * pv;
                p++;
            }
        }
        float4* qo = (float4*)(gQ + (size_t)row * 12);
        qo[0] = make_float4(q[0] * inv, q[1] * inv, q[2]  * inv, q[3]  * inv);
        qo[1] = make_float4(q[4] * inv, q[5] * inv, q[6]  * inv, q[7]  * inv);
        qo[2] = make_float4(q[8] * inv, q[9] * inv, q[10] * inv, q[11] * inv);
    }
}

// ---------------------------------------------------------------------------
// Stats: read gQ, accumulate 90 moments; write gPartial[moment][block].
// ---------------------------------------------------------------------------
__global__ void __launch_bounds__(ST_TPB, 2) stats_kernel(int B)
{
    __shared__ float sred[8 * 90];
    float mom[90];
#pragma unroll
    for (int v = 0; v < 90; v++) mom[v] = 0.f;

    int base = blockIdx.x * (ST_TPB * ST_ROWS) + threadIdx.x;
#pragma unroll
    for (int t = 0; t < ST_ROWS; t++) {
        int row = base + t * ST_TPB;
        if (row >= B) continue;
        const float4* qp = (const float4*)(gQ + (size_t)row * 12);
        float4 q0 = qp[0], q1 = qp[1], q2 = qp[2];
        float q[12] = {q0.x, q0.y, q0.z, q0.w, q1.x, q1.y, q1.z, q1.w,
                       q2.x, q2.y, q2.z, q2.w};
#pragma unroll
        for (int j = 0; j < 12; j++) mom[j] += q[j];
        int m = 12;
#pragma unroll
        for (int j = 0; j < 12; j++)
#pragma unroll
            for (int k = j; k < 12; k++) { mom[m] += q[j] * q[k]; m++; }
    }

    int lane = threadIdx.x & 31, warp = threadIdx.x >> 5;
#pragma unroll
    for (int v = 0; v < 90; v++) {
        float s = mom[v];
        s += __shfl_down_sync(0xffffffffu, s, 16);
        s += __shfl_down_sync(0xffffffffu, s, 8);
        s += __shfl_down_sync(0xffffffffu, s, 4);
        s += __shfl_down_sync(0xffffffffu, s, 2);
        s += __shfl_down_sync(0xffffffffu, s, 1);
        if (lane == 0) sred[warp * 90 + v] = s;
    }
    __syncthreads();
    if (threadIdx.x < 90) {
        float s = 0.f;
#pragma unroll
        for (int w = 0; w < 8; w++) s += sred[w * 90 + threadIdx.x];
        gPartial[threadIdx.x * ST_MAXBLK + blockIdx.x] = s;   // transposed layout
    }
}

// ---------------------------------------------------------------------------
// Finalize: warp-per-moment coalesced reduction, then fold BN into W2/B2.
// ---------------------------------------------------------------------------
__global__ void __launch_bounds__(1024) finalize_kernel(
    const float* __restrict__ fc_w, const float* __restrict__ fc_b,
    const float* __restrict__ gamma, const float* __restrict__ beta,
    int B, int nblocks)
{
    __shared__ double mom[90];
    int lane = threadIdx.x & 31, warp = threadIdx.x >> 5;

    for (int m = warp; m < 90; m += 32) {
        double s = 0.0;
        for (int b = lane; b < nblocks; b += 32)
            s += (double)gPartial[m * ST_MAXBLK + b];
        // warp reduce (double via two 32-bit shuffles handled by compiler)
        for (int off = 16; off > 0; off >>= 1)
            s += __shfl_down_sync(0xffffffffu, s, off);
        if (lane == 0) mom[m] = s;
    }
    __syncthreads();

    int tid = threadIdx.x;
    if (tid < 128) {
        double invB = 1.0 / (double)B;
        double m[12], wv[12];
        for (int j = 0; j < 12; j++) { m[j] = mom[j] * invB; wv[j] = (double)fc_w[tid * 12 + j]; }
        double mu = (double)fc_b[tid];
        for (int j = 0; j < 12; j++) mu += wv[j] * m[j];
        double var = 0.0;
        int idx = 12;
        for (int j = 0; j < 12; j++)
            for (int k = j; k < 12; k++) {
                double cjk = mom[idx] * invB - m[j] * m[k];
                double t = wv[j] * wv[k] * cjk;
                var += (j == k) ? t : 2.0 * t;
                idx++;
            }
        double s = (double)gamma[tid] / sqrt(var + 1e-5);
        for (int j = 0; j < 12; j++) gW2[tid * 12 + j] = (float)(wv[j] * s);
        gB2[tid] = (float)((double)beta[tid] + s * ((double)fc_b[tid] - mu));
    }
}

// ---------------------------------------------------------------------------
// Pass 2: warp-per-row, 2 rows per iteration for MLP. Lane l owns channels
// 4l..4l+3; one coalesced float4 streaming store per lane per row.
// ---------------------------------------------------------------------------
__global__ void __launch_bounds__(P2_TPB) pass2_kernel(float* __restrict__ out, int B)
{
    __shared__ float sW[128 * 12];
    for (int i = threadIdx.x; i < 128 * 12; i += P2_TPB) sW[i] = gW2[i];
    __syncthreads();

    int lane = threadIdx.x & 31;
    int c0 = lane * 4;
    float w[48];
#pragma unroll
    for (int c = 0; c < 4; c++) {
        const float4* wp = (const float4*)(sW + (c0 + c) * 12);
        float4 a = wp[0], b4 = wp[1], d = wp[2];
        w[c * 12 + 0] = a.x;  w[c * 12 + 1] = a.y;  w[c * 12 + 2]  = a.z;  w[c * 12 + 3]  = a.w;
        w[c * 12 + 4] = b4.x; w[c * 12 + 5] = b4.y; w[c * 12 + 6]  = b4.z; w[c * 12 + 7]  = b4.w;
        w[c * 12 + 8] = d.x;  w[c * 12 + 9] = d.y;  w[c * 12 + 10] = d.z;  w[c * 12 + 11] = d.w;
    }
    float4 bias = __ldg(((const float4*)gB2) + lane);

    int warp_id = (blockIdx.x * (P2_TPB / 32)) + (threadIdx.x >> 5);
    int nwarps  = gridDim.x * (P2_TPB / 32);

    for (int row = warp_id * 2; row < B; row += nwarps * 2) {
        int row1 = row + 1;
        const float4* qp0 = (const float4*)(gQ + (size_t)row * 12);
        float4 a0 = __ldg(qp0), a1 = __ldg(qp0 + 1), a2 = __ldg(qp0 + 2);
        float4 b0, b1, b2;
        bool has2 = (row1 < B);
        if (has2) {
            const float4* qp1 = (const float4*)(gQ + (size_t)row1 * 12);
            b0 = __ldg(qp1); b1 = __ldg(qp1 + 1); b2 = __ldg(qp1 + 2);
        }
        {
            float q[12] = {a0.x, a0.y, a0.z, a0.w, a1.x, a1.y, a1.z, a1.w,
                           a2.x, a2.y, a2.z, a2.w};
            float s0 = bias.x, s1 = bias.y, s2 = bias.z, s3 = bias.w;
#pragma unroll
            for (int j = 0; j < 12; j++) {
                float qv = q[j];
                s0 += qv * w[j]; s1 += qv * w[12 + j]; s2 += qv * w[24 + j]; s3 += qv * w[36 + j];
            }
            float4 o = make_float4(fmaxf(s0, 0.f), fmaxf(s1, 0.f), fmaxf(s2, 0.f), fmaxf(s3, 0.f));
            __stcs((float4*)(out + (size_t)row * 128 + c0), o);
        }
        if (has2) {
            float q[12] = {b0.x, b0.y, b0.z, b0.w, b1.x, b1.y, b1.z, b1.w,
                           b2.x, b2.y, b2.z, b2.w};
            float s0 = bias.x, s1 = bias.y, s2 = bias.z, s3 = bias.w;
#pragma unroll
            for (int j = 0; j < 12; j++) {
                float qv = q[j];
                s0 += qv * w[j]; s1 += qv * w[12 + j]; s2 += qv * w[24 + j]; s3 += qv * w[36 + j];
            }
            float4 o = make_float4(fmaxf(s0, 0.f), fmaxf(s1, 0.f), fmaxf(s2, 0.f), fmaxf(s3, 0.f));
            __stcs((float4*)(out + (size_t)row1 * 128 + c0), o);
        }
    }
}

// ---------------------------------------------------------------------------
extern "C" void kernel_launch(void* const* d_in, const int* in_sizes, int n_in,
                              void* d_out, int out_size)
{
    const float* x  = (const float*)d_in[0];
    const float* p1 = (const float*)d_in[1];
    const float* p2 = (const float*)d_in[2];
    const float* p3 = (const float*)d_in[3];
    const float* fw = (const float*)d_in[4];
    const float* fb = (const float*)d_in[5];
    const float* gm = (const float*)d_in[6];
    const float* bt = (const float*)d_in[7];
    float* out = (float*)d_out;

    int B  = in_sizes[0] / 16;
    if (B > MAXB) B = MAXB;
    int g1 = (B + P1_TPB * P1_ROWS - 1) / (P1_TPB * P1_ROWS);
    int gs = (B + ST_TPB * ST_ROWS - 1) / (ST_TPB * ST_ROWS);
    if (gs > ST_MAXBLK) gs = ST_MAXBLK;

    setup_kernel<<<1, 128>>>(p1, p2, p3);
    pass1_kernel<<<g1, P1_TPB>>>(x, B);
    stats_kernel<<<gs, ST_TPB>>>(B);
    finalize_kernel<<<1, 1024>>>(fw, fb, gm, bt, B, gs);
    pass2_kernel<<<P2_BLKS, P2_TPB>>>(out, B);
}